// round 4
// baseline (speedup 1.0000x reference)
#include <cuda_runtime.h>
#include <cstdint>

#define NFEAT 20000
#define DOUT  256
#define BATCH 4096
#define KD    64

// ---------------- scratch (static device globals; no runtime allocation) ----
__device__ float g_Z[(size_t)DOUT * NFEAT];              // zpre[d][n]
__device__ unsigned long long g_pack[DOUT * 256];        // (f2o(val)<<32)|idx, desc per row
__device__ int   g_sel[DOUT];                            // selected column per row d

// orderable-uint mapping for floats (monotone increasing)
__device__ __forceinline__ uint32_t f2o(float f) {
    uint32_t b = __float_as_uint(f);
    return (b & 0x80000000u) ? ~b : (b | 0x80000000u);
}
__device__ __forceinline__ float o2f(uint32_t m) {
    uint32_t b = (m & 0x80000000u) ? (m & 0x7fffffffu) : ~m;
    return __uint_as_float(b);
}

// ---------------- FFMA-only transcendentals (no MUFU, ~1-2 ulp) -------------
__device__ __forceinline__ float fast_log(float x) {      // x normal, > 0
    int i = __float_as_int(x);
    int e = (i - 0x3f3504f3) & 0xff800000;                // mantissa in [sqrt(.5), sqrt(2))
    float m = __int_as_float(i - e);
    float fe = (float)(e >> 23);
    float f = m - 1.0f;
    float z = f * f;
    float p = 7.0376836292e-2f;
    p = fmaf(p, f, -1.1514610310e-1f);
    p = fmaf(p, f,  1.1676998740e-1f);
    p = fmaf(p, f, -1.2420140846e-1f);
    p = fmaf(p, f,  1.4249322787e-1f);
    p = fmaf(p, f, -1.6668057665e-1f);
    p = fmaf(p, f,  2.0000714765e-1f);
    p = fmaf(p, f, -2.4999993993e-1f);
    p = fmaf(p, f,  3.3333331174e-1f);
    float y = p * f * z;
    y = fmaf(fe, -2.12194440e-4f, y);
    y = fmaf(-0.5f, z, y);
    float r = f + y;
    return fmaf(fe, 0.693359375f, r);
}

__device__ __forceinline__ float fast_exp(float x) {      // |x| < ~80
    const float LOG2E = 1.4426950408889634f;
    float fr = fmaf(x, LOG2E, 12582912.0f);               // round-to-nearest in low bits
    int ti = __float_as_int(fr) - 0x4B400000;             // integer part
    float r = fr - 12582912.0f;
    float f = fmaf(r, -0.693359375f, x);
    f = fmaf(r, 2.12194440e-4f, f);
    float p = 1.9875691500e-4f;
    p = fmaf(p, f, 1.3981999507e-3f);
    p = fmaf(p, f, 8.3334519073e-3f);
    p = fmaf(p, f, 4.1665795894e-2f);
    p = fmaf(p, f, 1.6666665459e-1f);
    p = fmaf(p, f, 5.0000001201e-1f);
    float zz = f * f;
    float e = fmaf(p, zz, f) + 1.0f;
    return __int_as_float(__float_as_int(e) + (ti << 23));
}

// ---------------------------------------------------------------------------
// K1: M = u @ tinyW (20000x256, K=64) with packed f32x2 FMA, softmax over 256,
//     zpre = ln10 + clamp(logsoftmax). Warp = 4 features; lane holds d-pairs
//     d = 64j + 2*lane + {0,1}. Transpose via smem, coalesced g_Z[d][n] writes.
// ---------------------------------------------------------------------------
__global__ void __launch_bounds__(256) k1_gemm(const float* __restrict__ u,
                                               const float* __restrict__ tinyW) {
    __shared__ float zs[32 * 258];                         // 33 KB
    const int t = threadIdx.x, lane = t & 31, w = t >> 5;
    const int n0 = blockIdx.x * 32;
    const int fb = n0 + w * 4;

    unsigned long long acc2[4][4];                         // [d-pair j][feature i]
#pragma unroll
    for (int j = 0; j < 4; j++)
#pragma unroll
        for (int i = 0; i < 4; i++) acc2[j][i] = 0ull;

    const float2* tw2 = reinterpret_cast<const float2*>(tinyW);
#pragma unroll 1
    for (int k = 0; k < KD; k += 4) {
        float4 uv[4];
#pragma unroll
        for (int i = 0; i < 4; i++)
            uv[i] = *reinterpret_cast<const float4*>(u + (size_t)(fb + i) * KD + k);
#pragma unroll
        for (int kk = 0; kk < 4; kk++) {
            unsigned long long wp[4];
#pragma unroll
            for (int j = 0; j < 4; j++) {
                float2 wv = __ldg(&tw2[(size_t)(k + kk) * 128 + j * 32 + lane]);
                asm("mov.b64 %0, {%1, %2};" : "=l"(wp[j]) : "f"(wv.x), "f"(wv.y));
            }
#pragma unroll
            for (int i = 0; i < 4; i++) {
                float uk = (kk == 0) ? uv[i].x : (kk == 1) ? uv[i].y
                         : (kk == 2) ? uv[i].z : uv[i].w;
                unsigned long long up;
                asm("mov.b64 %0, {%1, %1};" : "=l"(up) : "f"(uk));
#pragma unroll
                for (int j = 0; j < 4; j++)
                    asm("fma.rn.f32x2 %0, %1, %2, %0;"
                        : "+l"(acc2[j][i]) : "l"(up), "l"(wp[j]));
            }
        }
    }

    const float LN10  = 2.302585092994046f;
    const float LNEPS = -16.118095650958319f;              // ln(1e-7)
    const float LNHI  = -1.0000000500000026e-7f;           // ln(0.9999999)
#pragma unroll
    for (int i = 0; i < 4; i++) {
        float v[8];
#pragma unroll
        for (int j = 0; j < 4; j++)
            asm("mov.b64 {%0, %1}, %2;" : "=f"(v[2*j]), "=f"(v[2*j+1]) : "l"(acc2[j][i]));
        float m = v[0];
#pragma unroll
        for (int j = 1; j < 8; j++) m = fmaxf(m, v[j]);
#pragma unroll
        for (int o = 16; o; o >>= 1) m = fmaxf(m, __shfl_xor_sync(0xffffffffu, m, o));
        float s = 0.f;
#pragma unroll
        for (int j = 0; j < 8; j++) s += fast_exp(v[j] - m);
#pragma unroll
        for (int o = 16; o; o >>= 1) s += __shfl_xor_sync(0xffffffffu, s, o);
        float lns = fast_log(s);
        float2* zrow = reinterpret_cast<float2*>(zs + (w * 4 + i) * 258);
#pragma unroll
        for (int j = 0; j < 4; j++) {
            float z0 = LN10 + fminf(fmaxf(v[2*j]   - m - lns, LNEPS), LNHI);
            float z1 = LN10 + fminf(fmaxf(v[2*j+1] - m - lns, LNEPS), LNHI);
            zrow[j * 32 + lane] = make_float2(z0, z1);
        }
    }
    __syncthreads();
    const int tx = t & 31, ty = t >> 5;
#pragma unroll 4
    for (int dd = ty; dd < DOUT; dd += 8)
        g_Z[(size_t)dd * NFEAT + n0 + tx] = zs[tx * 258 + dd];
}

// ---------------------------------------------------------------------------
// K3: one CTA per row d. z = (zpre + gumbel)*invtemp in regs (float4 loads,
//     poly log/exp), c = rowmax + log(sumexp), binary-search top-256 threshold,
//     collect, bitonic-sort, emit packed (f2o(z-c), idx).
// ---------------------------------------------------------------------------
__global__ void __launch_bounds__(512) k3_select(const float* __restrict__ uniform) {
    const int d = blockIdx.x;
    const int t = threadIdx.x, lane = t & 31, w = t >> 5;
    __shared__ uint32_t shu[16];
    __shared__ float    shf[16];
    __shared__ int      shi[16];
    __shared__ unsigned long long skey[512];
    __shared__ int s_cnt;

    const float invt = 1.0f / 9.9999f;                    // temp = max(0.1, 10*0.99999)
    uint32_t mv[40];
    uint32_t mmax = 0;
    const float4* Z4 = reinterpret_cast<const float4*>(g_Z + (size_t)d * NFEAT);
    const float4* U4 = reinterpret_cast<const float4*>(uniform + (size_t)d * NFEAT);
#pragma unroll
    for (int i = 0; i < 10; i++) {
        int q = i * 512 + t;
        float4 zp, uu;
        if (q < NFEAT / 4) { zp = Z4[q]; uu = U4[q]; }
        else { zp = make_float4(0,0,0,0); uu = make_float4(.5f,.5f,.5f,.5f); }
        float g0 = -fast_log(-fast_log(uu.x));
        float g1 = -fast_log(-fast_log(uu.y));
        float g2 = -fast_log(-fast_log(uu.z));
        float g3 = -fast_log(-fast_log(uu.w));
        uint32_t m0 = f2o((zp.x + g0) * invt);
        uint32_t m1 = f2o((zp.y + g1) * invt);
        uint32_t m2 = f2o((zp.z + g2) * invt);
        uint32_t m3 = f2o((zp.w + g3) * invt);
        if (q >= NFEAT / 4) { m0 = m1 = m2 = m3 = 0u; }
        mv[4*i+0] = m0; mv[4*i+1] = m1; mv[4*i+2] = m2; mv[4*i+3] = m3;
        mmax = max(mmax, max(max(m0, m1), max(m2, m3)));
    }
#pragma unroll
    for (int o = 16; o; o >>= 1) mmax = max(mmax, __shfl_xor_sync(0xffffffffu, mmax, o));
    if (lane == 0) shu[w] = mmax;
    __syncthreads();
    uint32_t rmax_m = shu[0];
#pragma unroll
    for (int i = 1; i < 16; i++) rmax_m = max(rmax_m, shu[i]);
    const float rowmax = o2f(rmax_m);

    float ls = 0.f;
#pragma unroll
    for (int i = 0; i < 40; i++)
        if (mv[i]) ls += fast_exp(o2f(mv[i]) - rowmax);
#pragma unroll
    for (int o = 16; o; o >>= 1) ls += __shfl_xor_sync(0xffffffffu, ls, o);
    if (lane == 0) shf[w] = ls;
    __syncthreads();
    float ssum = 0.f;
#pragma unroll
    for (int i = 0; i < 16; i++) ssum += shf[i];
    const float c = rowmax + fast_log(ssum);

    // binary search: largest thr with count(mv >= thr) >= 256
    uint32_t lo = 0, hi = rmax_m;
    while (lo < hi) {
        uint32_t mid = lo + ((hi - lo) >> 1) + 1u;        // >= 1 excludes padding
        int cl = 0;
#pragma unroll
        for (int i = 0; i < 40; i++) cl += (mv[i] >= mid) ? 1 : 0;
#pragma unroll
        for (int o = 16; o; o >>= 1) cl += __shfl_xor_sync(0xffffffffu, cl, o);
        __syncthreads();
        if (lane == 0) shi[w] = cl;
        __syncthreads();
        int cnt = 0;
#pragma unroll
        for (int i = 0; i < 16; i++) cnt += shi[i];
        if (cnt >= 256) lo = mid; else hi = mid - 1;
    }

    if (t == 0) s_cnt = 0;
    __syncthreads();
    const uint32_t thr = lo;
#pragma unroll
    for (int i = 0; i < 40; i++)
        if (mv[i] >= thr) {
            int n = (i >> 2) * 2048 + t * 4 + (i & 3);
            int p = atomicAdd(&s_cnt, 1);
            if (p < 512)
                skey[p] = ((unsigned long long)mv[i] << 32) | (uint32_t)(NFEAT - n);
        }
    __syncthreads();
    int cnt = s_cnt; if (cnt > 512) cnt = 512;
    if (t >= cnt) skey[t] = 0ull;
    __syncthreads();

    for (int k = 2; k <= 512; k <<= 1)
        for (int j = k >> 1; j > 0; j >>= 1) {
            int ixj = t ^ j;
            if (ixj > t) {
                unsigned long long a = skey[t], b = skey[ixj];
                if ((a > b) == ((t & k) == 0)) { skey[t] = b; skey[ixj] = a; }
            }
            __syncthreads();
        }

    if (t < 256) {
        unsigned long long kk = skey[511 - t];            // t-th largest
        float val = o2f((uint32_t)(kk >> 32)) - c;        // log-softmax value
        uint32_t idx = (uint32_t)(NFEAT - (int)(kk & 0xffffffffu));
        g_pack[d * 256 + t] = ((unsigned long long)f2o(val) << 32) | idx;
    }
}

// ---------------------------------------------------------------------------
// K4: warp-synchronous greedy assignment. Lane owns 8 rows (r = lane + 32j),
//     current keys in registers, two-phase __reduce_max_sync argmax,
//     candidate advance via packed u64 L2 loads. No block barriers.
// ---------------------------------------------------------------------------
__global__ void __launch_bounds__(32) k4_greedy() {
    __shared__ uint32_t used[(NFEAT + 31) / 32];          // 625 words
    const int lane = threadIdx.x;
    for (int i = lane; i < (NFEAT + 31) / 32; i += 32) used[i] = 0u;

    unsigned long long key[8]; int col[8]; int ptr[8];
#pragma unroll
    for (int j = 0; j < 8; j++) {
        int r = lane + 32 * j;
        unsigned long long pk = __ldg(&g_pack[r * 256]);
        key[j] = (pk & 0xffffffff00000000ull) | (uint32_t)(255 - r);
        col[j] = (int)(uint32_t)pk;
        ptr[j] = 0;
    }
    __syncwarp();

    for (int step = 0; step < 256; step++) {
        unsigned long long best = key[0];
#pragma unroll
        for (int j = 1; j < 8; j++) best = (key[j] > best) ? key[j] : best;
        uint32_t hi = (uint32_t)(best >> 32);
        uint32_t wm = __reduce_max_sync(0xffffffffu, hi);
        uint32_t lo = (hi == wm) ? (uint32_t)best : 0u;
        uint32_t wl = __reduce_max_sync(0xffffffffu, lo);
        int x = 255 - (int)wl;                            // winning row
        int owner = x & 31, jx = x >> 5;
        int myc = 0;
#pragma unroll
        for (int j = 0; j < 8; j++) myc = (j == jx) ? col[j] : myc;
        int y = __shfl_sync(0xffffffffu, myc, owner);     // winning column
        if (lane == owner) {
            g_sel[x] = y;
#pragma unroll
            for (int j = 0; j < 8; j++) if (j == jx) key[j] = 0ull;
            used[y >> 5] |= (1u << (y & 31));
        }
        __syncwarp();
#pragma unroll
        for (int j = 0; j < 8; j++) {
            if (key[j] != 0ull && col[j] == y) {
                int r = lane + 32 * j;
                int p = ptr[j];
                unsigned long long pk; int cc;
                do {
                    p++;
                    pk = __ldg(&g_pack[r * 256 + p]);
                    cc = (int)(uint32_t)pk;
                } while (p < 255 && ((used[cc >> 5] >> (cc & 31)) & 1u));
                ptr[j] = p; col[j] = cc;
                key[j] = (pk & 0xffffffff00000000ull) | (uint32_t)(255 - r);
            }
        }
        __syncwarp();
    }
}

// ---------------------------------------------------------------------------
// K5: Y[b,d] = X[b, sel[d]] — one-hot matmul is a gather. 8 batched loads
//     per thread (MLP 8), coalesced writes.
// ---------------------------------------------------------------------------
__global__ void __launch_bounds__(256) k5_gather(const float* __restrict__ X,
                                                 float* __restrict__ Y) {
    __shared__ int scol[256];
    scol[threadIdx.x] = g_sel[threadIdx.x];
    __syncthreads();
    const int b0 = blockIdx.x * 8;
    const int dd = threadIdx.x;
    const int c = scol[dd];
    float v[8];
#pragma unroll
    for (int j = 0; j < 8; j++)
        v[j] = __ldg(X + (size_t)(b0 + j) * NFEAT + c);
#pragma unroll
    for (int j = 0; j < 8; j++)
        Y[(size_t)(b0 + j) * DOUT + dd] = v[j];
}

// ---------------------------------------------------------------------------
extern "C" void kernel_launch(void* const* d_in, const int* in_sizes, int n_in,
                              void* d_out, int out_size) {
    const float* X       = (const float*)d_in[0];   // (4096, 20000)
    const float* u       = (const float*)d_in[1];   // (20000, 64)
    const float* tinyW   = (const float*)d_in[2];   // (64, 256)
    const float* uniform = (const float*)d_in[3];   // (256, 20000)
    float* Y = (float*)d_out;                       // (4096, 256)

    k1_gemm  <<<NFEAT / 32, 256>>>(u, tinyW);
    k3_select<<<DOUT, 512>>>(uniform);
    k4_greedy<<<1, 32>>>();
    k5_gather<<<BATCH / 8, 256>>>(X, Y);
}

// round 5
// speedup vs baseline: 1.6936x; 1.6936x over previous
#include <cuda_runtime.h>
#include <cstdint>

#define NFEAT 20000
#define DOUT  256
#define BATCH 4096
#define KD    64

// ---------------- scratch (static device globals; no runtime allocation) ----
__device__ float g_Z[(size_t)DOUT * NFEAT];              // zpre[d][n]
__device__ unsigned long long g_pack[DOUT * 256];        // (f2o(val)<<32)|idx, desc per row
__device__ int   g_sel[DOUT];                            // selected column per row d

// orderable-uint mapping for floats (monotone increasing)
__device__ __forceinline__ uint32_t f2o(float f) {
    uint32_t b = __float_as_uint(f);
    return (b & 0x80000000u) ? ~b : (b | 0x80000000u);
}
__device__ __forceinline__ float o2f(uint32_t m) {
    uint32_t b = (m & 0x80000000u) ? (m & 0x7fffffffu) : ~m;
    return __uint_as_float(b);
}

// ---------------- FFMA-only transcendentals (no MUFU, ~1-2 ulp) -------------
__device__ __forceinline__ float fast_log(float x) {      // x normal, > 0
    int i = __float_as_int(x);
    int e = (i - 0x3f3504f3) & 0xff800000;
    float m = __int_as_float(i - e);
    float fe = (float)(e >> 23);
    float f = m - 1.0f;
    float z = f * f;
    float p = 7.0376836292e-2f;
    p = fmaf(p, f, -1.1514610310e-1f);
    p = fmaf(p, f,  1.1676998740e-1f);
    p = fmaf(p, f, -1.2420140846e-1f);
    p = fmaf(p, f,  1.4249322787e-1f);
    p = fmaf(p, f, -1.6668057665e-1f);
    p = fmaf(p, f,  2.0000714765e-1f);
    p = fmaf(p, f, -2.4999993993e-1f);
    p = fmaf(p, f,  3.3333331174e-1f);
    float y = p * f * z;
    y = fmaf(fe, -2.12194440e-4f, y);
    y = fmaf(-0.5f, z, y);
    float r = f + y;
    return fmaf(fe, 0.693359375f, r);
}

__device__ __forceinline__ float fast_exp(float x) {      // |x| < ~80
    const float LOG2E = 1.4426950408889634f;
    float fr = fmaf(x, LOG2E, 12582912.0f);
    int ti = __float_as_int(fr) - 0x4B400000;
    float r = fr - 12582912.0f;
    float f = fmaf(r, -0.693359375f, x);
    f = fmaf(r, 2.12194440e-4f, f);
    float p = 1.9875691500e-4f;
    p = fmaf(p, f, 1.3981999507e-3f);
    p = fmaf(p, f, 8.3334519073e-3f);
    p = fmaf(p, f, 4.1665795894e-2f);
    p = fmaf(p, f, 1.6666665459e-1f);
    p = fmaf(p, f, 5.0000001201e-1f);
    float zz = f * f;
    float e = fmaf(p, zz, f) + 1.0f;
    return __int_as_float(__float_as_int(e) + (ti << 23));
}

// ---------------------------------------------------------------------------
// K1: M = u @ tinyW (20000x256, K=64) with packed f32x2 FMA, softmax over 256,
//     zpre = ln10 + clamp(logsoftmax). Transpose via smem.
// ---------------------------------------------------------------------------
__global__ void __launch_bounds__(256) k1_gemm(const float* __restrict__ u,
                                               const float* __restrict__ tinyW) {
    __shared__ float zs[32 * 258];
    const int t = threadIdx.x, lane = t & 31, w = t >> 5;
    const int n0 = blockIdx.x * 32;
    const int fb = n0 + w * 4;

    unsigned long long acc2[4][4];
#pragma unroll
    for (int j = 0; j < 4; j++)
#pragma unroll
        for (int i = 0; i < 4; i++) acc2[j][i] = 0ull;

    const float2* tw2 = reinterpret_cast<const float2*>(tinyW);
#pragma unroll 1
    for (int k = 0; k < KD; k += 4) {
        float4 uv[4];
#pragma unroll
        for (int i = 0; i < 4; i++)
            uv[i] = *reinterpret_cast<const float4*>(u + (size_t)(fb + i) * KD + k);
#pragma unroll
        for (int kk = 0; kk < 4; kk++) {
            unsigned long long wp[4];
#pragma unroll
            for (int j = 0; j < 4; j++) {
                float2 wv = __ldg(&tw2[(size_t)(k + kk) * 128 + j * 32 + lane]);
                asm("mov.b64 %0, {%1, %2};" : "=l"(wp[j]) : "f"(wv.x), "f"(wv.y));
            }
#pragma unroll
            for (int i = 0; i < 4; i++) {
                float uk = (kk == 0) ? uv[i].x : (kk == 1) ? uv[i].y
                         : (kk == 2) ? uv[i].z : uv[i].w;
                unsigned long long up;
                asm("mov.b64 %0, {%1, %1};" : "=l"(up) : "f"(uk));
#pragma unroll
                for (int j = 0; j < 4; j++)
                    asm("fma.rn.f32x2 %0, %1, %2, %0;"
                        : "+l"(acc2[j][i]) : "l"(up), "l"(wp[j]));
            }
        }
    }

    const float LN10  = 2.302585092994046f;
    const float LNEPS = -16.118095650958319f;
    const float LNHI  = -1.0000000500000026e-7f;
#pragma unroll
    for (int i = 0; i < 4; i++) {
        float v[8];
#pragma unroll
        for (int j = 0; j < 4; j++)
            asm("mov.b64 {%0, %1}, %2;" : "=f"(v[2*j]), "=f"(v[2*j+1]) : "l"(acc2[j][i]));
        float m = v[0];
#pragma unroll
        for (int j = 1; j < 8; j++) m = fmaxf(m, v[j]);
#pragma unroll
        for (int o = 16; o; o >>= 1) m = fmaxf(m, __shfl_xor_sync(0xffffffffu, m, o));
        float s = 0.f;
#pragma unroll
        for (int j = 0; j < 8; j++) s += fast_exp(v[j] - m);
#pragma unroll
        for (int o = 16; o; o >>= 1) s += __shfl_xor_sync(0xffffffffu, s, o);
        float lns = fast_log(s);
        float2* zrow = reinterpret_cast<float2*>(zs + (w * 4 + i) * 258);
#pragma unroll
        for (int j = 0; j < 4; j++) {
            float z0 = LN10 + fminf(fmaxf(v[2*j]   - m - lns, LNEPS), LNHI);
            float z1 = LN10 + fminf(fmaxf(v[2*j+1] - m - lns, LNEPS), LNHI);
            zrow[j * 32 + lane] = make_float2(z0, z1);
        }
    }
    __syncthreads();
    const int tx = t & 31, ty = t >> 5;
#pragma unroll 4
    for (int dd = ty; dd < DOUT; dd += 8)
        g_Z[(size_t)dd * NFEAT + n0 + tx] = zs[tx * 258 + dd];
}

// ---------------------------------------------------------------------------
// K3 (rewritten): one CTA per row d. Values computed ONCE into dynamic smem
//     zv[20000] (no register arrays -> no spills). Exact 256th-largest via
//     3-level radix select (2048/2048/1024-bucket histograms). Collect + sort.
// ---------------------------------------------------------------------------
#define K3_DSMEM (80000 + 8192)   // zv[20000] u32 + hist[2048] u32 (skey aliases hist)

__global__ void __launch_bounds__(512) k3_select(const float* __restrict__ uniform) {
    extern __shared__ unsigned char dyn[];
    uint32_t* zv   = reinterpret_cast<uint32_t*>(dyn);           // 20000 u32
    uint32_t* hist = reinterpret_cast<uint32_t*>(dyn + 80000);   // 2048  u32
    unsigned long long* skey = reinterpret_cast<unsigned long long*>(dyn + 80000);

    __shared__ uint32_t shu[16];
    __shared__ float    shf[16];
    __shared__ uint32_t s_b, s_knew;
    __shared__ int      s_cnt;

    const int d = blockIdx.x;
    const int t = threadIdx.x, lane = t & 31, w = t >> 5;
    const float invt = 1.0f / 9.9999f;            // temp = max(0.1, 10*0.99999)

    // ---- pass 1: compute mapped values once, store to smem, track max ----
    const float4* Z4 = reinterpret_cast<const float4*>(g_Z + (size_t)d * NFEAT);
    const float4* U4 = reinterpret_cast<const float4*>(uniform + (size_t)d * NFEAT);
    uint32_t mmax = 0;
#pragma unroll
    for (int i = 0; i < 10; i++) {
        int q = i * 512 + t;
        if (q < NFEAT / 4) {
            float4 zp = Z4[q], uu = U4[q];
            // z = (zpre + gumbel)/temp, gumbel = -log(-log(u))
            uint32_t m0 = f2o((zp.x - fast_log(-fast_log(uu.x))) * invt);
            uint32_t m1 = f2o((zp.y - fast_log(-fast_log(uu.y))) * invt);
            uint32_t m2 = f2o((zp.z - fast_log(-fast_log(uu.z))) * invt);
            uint32_t m3 = f2o((zp.w - fast_log(-fast_log(uu.w))) * invt);
            zv[4*q+0] = m0; zv[4*q+1] = m1; zv[4*q+2] = m2; zv[4*q+3] = m3;
            mmax = max(mmax, max(max(m0, m1), max(m2, m3)));
        }
    }
#pragma unroll
    for (int o = 16; o; o >>= 1) mmax = max(mmax, __shfl_xor_sync(0xffffffffu, mmax, o));
    if (lane == 0) shu[w] = mmax;
    __syncthreads();
    uint32_t rmax_m = shu[0];
#pragma unroll
    for (int i = 1; i < 16; i++) rmax_m = max(rmax_m, shu[i]);
    const float rowmax = o2f(rmax_m);

    // ---- pass 2: sum exp(z - rowmax) from smem ----
    float ls = 0.f;
    for (int n = t; n < NFEAT; n += 512)
        ls += fast_exp(o2f(zv[n]) - rowmax);
#pragma unroll
    for (int o = 16; o; o >>= 1) ls += __shfl_xor_sync(0xffffffffu, ls, o);
    if (lane == 0) shf[w] = ls;
    __syncthreads();
    float ssum = 0.f;
#pragma unroll
    for (int i = 0; i < 16; i++) ssum += shf[i];
    const float c = rowmax + fast_log(ssum);       // logsumexp offset

    // ---- radix select: exact 256th-largest mapped value ----
    uint32_t uprefix = 0, kk = 256;
#pragma unroll
    for (int lvl = 0; lvl < 3; lvl++) {
        const int shift = (lvl == 0) ? 21 : (lvl == 1) ? 10 : 0;
        const int width = (lvl == 2) ? 10 : 11;
        const int nb = 1 << width;
        for (int i = t; i < nb; i += 512) hist[i] = 0u;
        __syncthreads();
        for (int n = t; n < NFEAT; n += 512) {
            uint32_t v = zv[n];
            bool ok = (lvl == 0) || ((v >> (shift + width)) == uprefix);
            if (ok) atomicAdd(&hist[(v >> shift) & (nb - 1)], 1u);
        }
        __syncthreads();
        if (t < 32) {                               // warp 0: suffix-scan top-down
            const int chunk = nb >> 5;
            const int base = nb - 1 - lane * chunk;
            uint32_t S = 0;
            for (int j = 0; j < chunk; j++) S += hist[base - j];
            uint32_t cum = S;
#pragma unroll
            for (int o = 1; o < 32; o <<= 1) {
                uint32_t vv = __shfl_up_sync(0xffffffffu, cum, o);
                if (lane >= o) cum += vv;
            }
            uint32_t excl = cum - S;                // count in buckets above my chunk
            if (excl < kk && excl + S >= kk) {
                uint32_t c2 = excl;
                for (int j = 0; j < chunk; j++) {
                    uint32_t h = hist[base - j];
                    if (c2 + h >= kk) { s_b = (uint32_t)(base - j); s_knew = kk - c2; break; }
                    c2 += h;
                }
            }
        }
        __syncthreads();
        uprefix = (uprefix << width) | s_b;
        kk = s_knew;
        __syncthreads();
    }
    const uint32_t thr = uprefix;                   // exact 256th-largest value

    // ---- collect candidates >= thr (values distinct => ~256), sort ----
    if (t == 0) s_cnt = 0;
    __syncthreads();
    for (int n = t; n < NFEAT; n += 512) {
        uint32_t v = zv[n];
        if (v >= thr) {
            int p = atomicAdd(&s_cnt, 1);
            if (p < 512)
                skey[p] = ((unsigned long long)v << 32) | (uint32_t)(NFEAT - n);
        }
    }
    __syncthreads();
    int cnt = s_cnt; if (cnt > 512) cnt = 512;
    if (t >= cnt) skey[t] = 0ull;
    __syncthreads();

    for (int k = 2; k <= 512; k <<= 1)
        for (int j = k >> 1; j > 0; j >>= 1) {
            int ixj = t ^ j;
            if (ixj > t) {
                unsigned long long a = skey[t], b = skey[ixj];
                if ((a > b) == ((t & k) == 0)) { skey[t] = b; skey[ixj] = a; }
            }
            __syncthreads();
        }

    if (t < 256) {
        unsigned long long kv = skey[511 - t];      // t-th largest
        float val = o2f((uint32_t)(kv >> 32)) - c;  // log-softmax value
        uint32_t idx = (uint32_t)(NFEAT - (int)(kv & 0xffffffffu));
        g_pack[d * 256 + t] = ((unsigned long long)f2o(val) << 32) | idx;
    }
}

// ---------------------------------------------------------------------------
// K4: warp-synchronous greedy assignment (lane owns 8 rows, REDUX argmax).
// ---------------------------------------------------------------------------
__global__ void __launch_bounds__(32) k4_greedy() {
    __shared__ uint32_t used[(NFEAT + 31) / 32];
    const int lane = threadIdx.x;
    for (int i = lane; i < (NFEAT + 31) / 32; i += 32) used[i] = 0u;

    unsigned long long key[8]; int col[8]; int ptr[8];
#pragma unroll
    for (int j = 0; j < 8; j++) {
        int r = lane + 32 * j;
        unsigned long long pk = __ldg(&g_pack[r * 256]);
        key[j] = (pk & 0xffffffff00000000ull) | (uint32_t)(255 - r);
        col[j] = (int)(uint32_t)pk;
        ptr[j] = 0;
    }
    __syncwarp();

    for (int step = 0; step < 256; step++) {
        unsigned long long best = key[0];
#pragma unroll
        for (int j = 1; j < 8; j++) best = (key[j] > best) ? key[j] : best;
        uint32_t hi = (uint32_t)(best >> 32);
        uint32_t wm = __reduce_max_sync(0xffffffffu, hi);
        uint32_t lo = (hi == wm) ? (uint32_t)best : 0u;
        uint32_t wl = __reduce_max_sync(0xffffffffu, lo);
        int x = 255 - (int)wl;
        int owner = x & 31, jx = x >> 5;
        int myc = 0;
#pragma unroll
        for (int j = 0; j < 8; j++) myc = (j == jx) ? col[j] : myc;
        int y = __shfl_sync(0xffffffffu, myc, owner);
        if (lane == owner) {
            g_sel[x] = y;
#pragma unroll
            for (int j = 0; j < 8; j++) if (j == jx) key[j] = 0ull;
            used[y >> 5] |= (1u << (y & 31));
        }
        __syncwarp();
#pragma unroll
        for (int j = 0; j < 8; j++) {
            if (key[j] != 0ull && col[j] == y) {
                int r = lane + 32 * j;
                int p = ptr[j];
                unsigned long long pk; int cc;
                do {
                    p++;
                    pk = __ldg(&g_pack[r * 256 + p]);
                    cc = (int)(uint32_t)pk;
                } while (p < 255 && ((used[cc >> 5] >> (cc & 31)) & 1u));
                ptr[j] = p; col[j] = cc;
                key[j] = (pk & 0xffffffff00000000ull) | (uint32_t)(255 - r);
            }
        }
        __syncwarp();
    }
}

// ---------------------------------------------------------------------------
// K5: Y[b,d] = X[b, sel[d]] — gather, L2-only loads (no reuse), 4 rows/thread.
// ---------------------------------------------------------------------------
__global__ void __launch_bounds__(256) k5_gather(const float* __restrict__ X,
                                                 float* __restrict__ Y) {
    __shared__ int scol[256];
    scol[threadIdx.x] = g_sel[threadIdx.x];
    __syncthreads();
    const int b0 = blockIdx.x * 4;
    const int dd = threadIdx.x;
    const int c = scol[dd];
    float v[4];
#pragma unroll
    for (int j = 0; j < 4; j++)
        v[j] = __ldcg(X + (size_t)(b0 + j) * NFEAT + c);
#pragma unroll
    for (int j = 0; j < 4; j++)
        Y[(size_t)(b0 + j) * DOUT + dd] = v[j];
}

// ---------------------------------------------------------------------------
extern "C" void kernel_launch(void* const* d_in, const int* in_sizes, int n_in,
                              void* d_out, int out_size) {
    const float* X       = (const float*)d_in[0];   // (4096, 20000)
    const float* u       = (const float*)d_in[1];   // (20000, 64)
    const float* tinyW   = (const float*)d_in[2];   // (64, 256)
    const float* uniform = (const float*)d_in[3];   // (256, 20000)
    float* Y = (float*)d_out;                       // (4096, 256)

    static bool attr_done = false;
    if (!attr_done) {
        cudaFuncSetAttribute(k3_select,
                             cudaFuncAttributeMaxDynamicSharedMemorySize, K3_DSMEM);
        attr_done = true;
    }

    k1_gemm  <<<NFEAT / 32, 256>>>(u, tinyW);
    k3_select<<<DOUT, 512, K3_DSMEM>>>(uniform);
    k4_greedy<<<1, 32>>>();
    k5_gather<<<BATCH / 4, 256>>>(X, Y);
}